// round 1
// baseline (speedup 1.0000x reference)
#include <cuda_runtime.h>
#include <cstdint>
#include <math.h>

// Problem constants
#define HEADS   8
#define SEQ     2048
#define DMODEL  2048
#define HDIM    256
#define BATCH   2
#define BHN     (BATCH*HEADS)      // 16
#define MROWS   (BATCH*SEQ)        // 4096
#define SCALING 0.0625f            // 256^-0.5

// ---------------- scratch (device globals; no allocation) ----------------
__device__ float g_q[BHN*SEQ*HDIM];    // [bh][s][hd]
__device__ float g_k[BHN*SEQ*HDIM];
__device__ float g_v[BHN*SEQ*HDIM];
__device__ float g_ao[MROWS*DMODEL];   // attention output in [b,s,D] layout
__device__ float g_linv[BHN*SEQ];      // 1/rowsum

// ---------------- helpers ----------------
__device__ __forceinline__ uint32_t f2tf32(float x) {
    uint32_t r;
    asm("cvt.rna.tf32.f32 %0, %1;" : "=r"(r) : "f"(x));
    return r;
}

__device__ __forceinline__ void mma_tf32(float c[4],
                                         uint32_t a0, uint32_t a1, uint32_t a2, uint32_t a3,
                                         uint32_t b0, uint32_t b1) {
    asm volatile(
        "mma.sync.aligned.m16n8k8.row.col.f32.tf32.tf32.f32 "
        "{%0,%1,%2,%3},{%4,%5,%6,%7},{%8,%9},{%0,%1,%2,%3};"
        : "+f"(c[0]), "+f"(c[1]), "+f"(c[2]), "+f"(c[3])
        : "r"(a0), "r"(a1), "r"(a2), "r"(a3), "r"(b0), "r"(b1));
}

// =====================================================================
// GEMM: Y[m,n] = sum_k A[m,k] * W[n,k] + bias[n]
// A: [4096, 2048] row-major, W: [2048, 2048] row-major (K contiguous both)
// MODE 0: write to [bh][s][hd] layout (QKV proj).  MODE 1: plain [m][n].
// =====================================================================
template <int MODE>
__global__ __launch_bounds__(256, 2)
void gemm_kernel(const float* __restrict__ A, const float* __restrict__ W,
                 const float* __restrict__ bias, float* __restrict__ out)
{
    __shared__ uint32_t sA[128][36];   // padded: conflict-free frag loads
    __shared__ uint32_t sB[128][36];

    const int tid  = threadIdx.x;
    const int lane = tid & 31;
    const int warp = tid >> 5;
    const int wm = warp & 3;          // 4 warps along M (32 rows each)
    const int wn = warp >> 2;         // 2 warps along N (64 cols each)
    const int g  = lane >> 2;
    const int t4 = lane & 3;

    const int m0 = blockIdx.y * 128;
    const int n0 = blockIdx.x * 128;

    float c[2][8][4];
    #pragma unroll
    for (int i = 0; i < 2; i++)
        #pragma unroll
        for (int j = 0; j < 8; j++)
            #pragma unroll
            for (int r = 0; r < 4; r++) c[i][j][r] = 0.f;

    const int lr = tid >> 3;          // 0..31
    const int lc = (tid & 7) << 2;    // 0,4,...,28

    for (int k0 = 0; k0 < DMODEL; k0 += 32) {
        #pragma unroll
        for (int i = 0; i < 4; i++) {
            int row = lr + 32 * i;
            float4 va = *(const float4*)(A + (size_t)(m0 + row) * DMODEL + k0 + lc);
            sA[row][lc]     = f2tf32(va.x);
            sA[row][lc + 1] = f2tf32(va.y);
            sA[row][lc + 2] = f2tf32(va.z);
            sA[row][lc + 3] = f2tf32(va.w);
            float4 vb = *(const float4*)(W + (size_t)(n0 + row) * DMODEL + k0 + lc);
            sB[row][lc]     = f2tf32(vb.x);
            sB[row][lc + 1] = f2tf32(vb.y);
            sB[row][lc + 2] = f2tf32(vb.z);
            sB[row][lc + 3] = f2tf32(vb.w);
        }
        __syncthreads();

        #pragma unroll
        for (int kk = 0; kk < 32; kk += 8) {
            uint32_t a[2][4];
            #pragma unroll
            for (int i = 0; i < 2; i++) {
                int row = wm * 32 + i * 16 + g;
                a[i][0] = sA[row][kk + t4];
                a[i][1] = sA[row + 8][kk + t4];
                a[i][2] = sA[row][kk + t4 + 4];
                a[i][3] = sA[row + 8][kk + t4 + 4];
            }
            uint32_t b[8][2];
            #pragma unroll
            for (int j = 0; j < 8; j++) {
                int col = wn * 64 + j * 8 + g;
                b[j][0] = sB[col][kk + t4];
                b[j][1] = sB[col][kk + t4 + 4];
            }
            #pragma unroll
            for (int i = 0; i < 2; i++)
                #pragma unroll
                for (int j = 0; j < 8; j++)
                    mma_tf32(c[i][j], a[i][0], a[i][1], a[i][2], a[i][3], b[j][0], b[j][1]);
        }
        __syncthreads();
    }

    // epilogue
    #pragma unroll
    for (int i = 0; i < 2; i++) {
        #pragma unroll
        for (int j = 0; j < 8; j++) {
            int row0 = m0 + wm * 32 + i * 16 + g;
            int col  = n0 + wn * 64 + j * 8 + 2 * t4;
            float b0 = bias[col], b1 = bias[col + 1];
            float2 v0 = make_float2(c[i][j][0] + b0, c[i][j][1] + b1);
            float2 v1 = make_float2(c[i][j][2] + b0, c[i][j][3] + b1);
            if (MODE == 0) {
                int bb = row0 >> 11, s = row0 & 2047, h = col >> 8, dd = col & 255;
                size_t base = (((size_t)bb * HEADS + h) * SEQ) * HDIM + dd;
                *(float2*)(out + base + (size_t)s * HDIM)       = v0;
                *(float2*)(out + base + (size_t)(s + 8) * HDIM) = v1;
            } else {
                *(float2*)(out + (size_t)row0 * DMODEL + col)       = v0;
                *(float2*)(out + (size_t)(row0 + 8) * DMODEL + col) = v1;
            }
        }
    }
}

// =====================================================================
// Attention kernel: per (bh, 64-row q tile).
// Pass 1: row max (no exp). Pass 2: e = exp(s-m) written UNNORMALIZED to
// probs region, accumulate l and O += e @ V. O scaled by 1/l at epilogue.
// =====================================================================
#define ATTN_SMEM_WORDS (3 * 64 * 260 + 64 * 68)
#define ATTN_SMEM_BYTES (ATTN_SMEM_WORDS * 4)

__device__ __forceinline__ void qk_tile(const uint32_t (*sQ)[260], const uint32_t (*sK)[260],
                                        int wq, int wk, int g, int t4, float c[4][4])
{
    #pragma unroll
    for (int nt = 0; nt < 4; nt++)
        #pragma unroll
        for (int r = 0; r < 4; r++) c[nt][r] = 0.f;
    #pragma unroll
    for (int kk = 0; kk < HDIM; kk += 8) {
        uint32_t a0 = sQ[wq * 16 + g][kk + t4];
        uint32_t a1 = sQ[wq * 16 + g + 8][kk + t4];
        uint32_t a2 = sQ[wq * 16 + g][kk + t4 + 4];
        uint32_t a3 = sQ[wq * 16 + g + 8][kk + t4 + 4];
        #pragma unroll
        for (int nt = 0; nt < 4; nt++) {
            int col = wk * 32 + nt * 8 + g;
            uint32_t b0 = sK[col][kk + t4];
            uint32_t b1 = sK[col][kk + t4 + 4];
            mma_tf32(c[nt], a0, a1, a2, a3, b0, b1);
        }
    }
}

__global__ __launch_bounds__(256, 1)
void attn_kernel(const float* __restrict__ Q, const float* __restrict__ Kp,
                 const float* __restrict__ Vp, float* __restrict__ probs,
                 float* __restrict__ ao, float* __restrict__ linv)
{
    extern __shared__ uint32_t dyn[];
    uint32_t (*sQ)[260] = reinterpret_cast<uint32_t(*)[260]>(dyn);
    uint32_t (*sK)[260] = reinterpret_cast<uint32_t(*)[260]>(dyn + 64 * 260);
    uint32_t (*sV)[260] = reinterpret_cast<uint32_t(*)[260]>(dyn + 2 * 64 * 260);
    float    (*sP)[68]  = reinterpret_cast<float(*)[68]>(dyn + 3 * 64 * 260);
    __shared__ float sRed[2][64];
    __shared__ float sM[64];
    __shared__ float sInv[64];

    const int tid = threadIdx.x, lane = tid & 31, warp = tid >> 5;
    const int wq = warp & 3;     // 4 warps along q (16 rows each)
    const int wk = warp >> 2;    // 2 warps along k-cols (S) / hd-cols (PV)
    const int g = lane >> 2, t4 = lane & 3;
    const int qt = blockIdx.x, bh = blockIdx.y;
    const int q0 = qt * 64;

    // load Q tile (64 x 256), tf32-rounded
    const float* Qg = Q + ((size_t)bh * SEQ + q0) * HDIM;
    for (int i = tid; i < 64 * 64; i += 256) {
        int r = i >> 6, cc = (i & 63) << 2;
        float4 v = *(const float4*)(Qg + (size_t)r * HDIM + cc);
        sQ[r][cc]     = f2tf32(v.x);
        sQ[r][cc + 1] = f2tf32(v.y);
        sQ[r][cc + 2] = f2tf32(v.z);
        sQ[r][cc + 3] = f2tf32(v.w);
    }

    const int qg0 = q0 + wq * 16 + g;
    const int qg1 = qg0 + 8;

    // ---------------- Pass 1: row max ----------------
    float m0r = -INFINITY, m1r = -INFINITY;
    for (int j = 0; j <= qt; j++) {
        __syncthreads();
        const float* Kg = Kp + ((size_t)bh * SEQ + j * 64) * HDIM;
        for (int i = tid; i < 64 * 64; i += 256) {
            int r = i >> 6, cc = (i & 63) << 2;
            float4 v = *(const float4*)(Kg + (size_t)r * HDIM + cc);
            sK[r][cc]     = f2tf32(v.x);
            sK[r][cc + 1] = f2tf32(v.y);
            sK[r][cc + 2] = f2tf32(v.z);
            sK[r][cc + 3] = f2tf32(v.w);
        }
        __syncthreads();
        float c4[4][4];
        qk_tile(sQ, sK, wq, wk, g, t4, c4);
        #pragma unroll
        for (int nt = 0; nt < 4; nt++) {
            int kg = j * 64 + wk * 32 + nt * 8 + 2 * t4;
            float s;
            s = c4[nt][0] * SCALING; if (kg     <= qg0 && s > m0r) m0r = s;
            s = c4[nt][1] * SCALING; if (kg + 1 <= qg0 && s > m0r) m0r = s;
            s = c4[nt][2] * SCALING; if (kg     <= qg1 && s > m1r) m1r = s;
            s = c4[nt][3] * SCALING; if (kg + 1 <= qg1 && s > m1r) m1r = s;
        }
    }
    m0r = fmaxf(m0r, __shfl_xor_sync(0xFFFFFFFFu, m0r, 1));
    m0r = fmaxf(m0r, __shfl_xor_sync(0xFFFFFFFFu, m0r, 2));
    m1r = fmaxf(m1r, __shfl_xor_sync(0xFFFFFFFFu, m1r, 1));
    m1r = fmaxf(m1r, __shfl_xor_sync(0xFFFFFFFFu, m1r, 2));
    if (t4 == 0) { sRed[wk][wq * 16 + g] = m0r; sRed[wk][wq * 16 + g + 8] = m1r; }
    __syncthreads();
    if (tid < 64) sM[tid] = fmaxf(sRed[0][tid], sRed[1][tid]);
    __syncthreads();

    const float mr0 = sM[wq * 16 + g];
    const float mr1 = sM[wq * 16 + g + 8];

    // ---------------- Pass 2 ----------------
    float l0 = 0.f, l1 = 0.f;
    float o[16][4];
    #pragma unroll
    for (int nt = 0; nt < 16; nt++)
        #pragma unroll
        for (int r = 0; r < 4; r++) o[nt][r] = 0.f;

    for (int j = 0; j <= qt; j++) {
        __syncthreads();
        const float* Kg = Kp + ((size_t)bh * SEQ + j * 64) * HDIM;
        const float* Vg = Vp + ((size_t)bh * SEQ + j * 64) * HDIM;
        for (int i = tid; i < 64 * 64; i += 256) {
            int r = i >> 6, cc = (i & 63) << 2;
            float4 v = *(const float4*)(Kg + (size_t)r * HDIM + cc);
            sK[r][cc]     = f2tf32(v.x);
            sK[r][cc + 1] = f2tf32(v.y);
            sK[r][cc + 2] = f2tf32(v.z);
            sK[r][cc + 3] = f2tf32(v.w);
            float4 w = *(const float4*)(Vg + (size_t)r * HDIM + cc);
            sV[r][cc]     = f2tf32(w.x);
            sV[r][cc + 1] = f2tf32(w.y);
            sV[r][cc + 2] = f2tf32(w.z);
            sV[r][cc + 3] = f2tf32(w.w);
        }
        __syncthreads();
        float c4[4][4];
        qk_tile(sQ, sK, wq, wk, g, t4, c4);

        #pragma unroll
        for (int nt = 0; nt < 4; nt++) {
            int kg  = j * 64 + wk * 32 + nt * 8 + 2 * t4;
            int col = wk * 32 + nt * 8 + 2 * t4;
            float e;
            e = (kg     <= qg0) ? __expf(c4[nt][0] * SCALING - mr0) : 0.f; l0 += e; sP[wq*16+g][col]     = e;
            e = (kg + 1 <= qg0) ? __expf(c4[nt][1] * SCALING - mr0) : 0.f; l0 += e; sP[wq*16+g][col+1]   = e;
            e = (kg     <= qg1) ? __expf(c4[nt][2] * SCALING - mr1) : 0.f; l1 += e; sP[wq*16+g+8][col]   = e;
            e = (kg + 1 <= qg1) ? __expf(c4[nt][3] * SCALING - mr1) : 0.f; l1 += e; sP[wq*16+g+8][col+1] = e;
        }
        __syncthreads();

        // write unnormalized e tile to probs gmem (coalesced)
        float* pg = probs + ((size_t)bh * SEQ + q0) * SEQ + j * 64;
        for (int i = tid; i < 64 * 16; i += 256) {
            int r = i >> 4, cc = (i & 15) << 2;
            *(float4*)(pg + (size_t)r * SEQ + cc) = *(const float4*)&sP[r][cc];
        }

        // O += P @ V  (warp tile 16 x 128, wk selects hd half)
        #pragma unroll
        for (int kk = 0; kk < 64; kk += 8) {
            uint32_t a0 = f2tf32(sP[wq * 16 + g][kk + t4]);
            uint32_t a1 = f2tf32(sP[wq * 16 + g + 8][kk + t4]);
            uint32_t a2 = f2tf32(sP[wq * 16 + g][kk + t4 + 4]);
            uint32_t a3 = f2tf32(sP[wq * 16 + g + 8][kk + t4 + 4]);
            #pragma unroll
            for (int nt = 0; nt < 16; nt++) {
                int vcol = wk * 128 + nt * 8 + g;
                uint32_t b0 = sV[kk + t4][vcol];
                uint32_t b1 = sV[kk + t4 + 4][vcol];
                mma_tf32(o[nt], a0, a1, a2, a3, b0, b1);
            }
        }
    }

    // merge l across quad and across the two wk halves
    l0 += __shfl_xor_sync(0xFFFFFFFFu, l0, 1);
    l0 += __shfl_xor_sync(0xFFFFFFFFu, l0, 2);
    l1 += __shfl_xor_sync(0xFFFFFFFFu, l1, 1);
    l1 += __shfl_xor_sync(0xFFFFFFFFu, l1, 2);
    __syncthreads();   // sRed reuse
    if (t4 == 0) { sRed[wk][wq * 16 + g] = l0; sRed[wk][wq * 16 + g + 8] = l1; }
    __syncthreads();
    if (tid < 64) {
        float inv = 1.0f / (sRed[0][tid] + sRed[1][tid]);
        sInv[tid] = inv;
        linv[(size_t)bh * SEQ + q0 + tid] = inv;
    }
    __syncthreads();

    // write O (scaled) to attn_out in [b, s, D] layout
    const float i0 = sInv[wq * 16 + g];
    const float i1 = sInv[wq * 16 + g + 8];
    const int bb = bh >> 3, hh = bh & 7;
    float* og = ao + ((size_t)bb * SEQ + q0) * DMODEL + hh * HDIM;
    #pragma unroll
    for (int nt = 0; nt < 16; nt++) {
        int col = wk * 128 + nt * 8 + 2 * t4;
        int r0 = wq * 16 + g, r1 = r0 + 8;
        *(float2*)(og + (size_t)r0 * DMODEL + col) = make_float2(o[nt][0] * i0, o[nt][1] * i0);
        *(float2*)(og + (size_t)r1 * DMODEL + col) = make_float2(o[nt][2] * i1, o[nt][3] * i1);
    }
}

// =====================================================================
// Rescale: probs[row][k] = e * inv_l for k <= q, else 0 (fills poisoned
// upper triangle). One block per row.
// =====================================================================
__global__ void rescale_kernel(float* __restrict__ probs, const float* __restrict__ linv)
{
    int row = blockIdx.x;                 // bh*SEQ + q
    int q = row & (SEQ - 1);
    float inv = linv[row];
    float* p = probs + (size_t)row * SEQ;
    for (int i = threadIdx.x; i < SEQ / 4; i += blockDim.x) {
        int k = i << 2;
        float4 v = *(float4*)(p + k);
        v.x = (k     <= q) ? v.x * inv : 0.f;
        v.y = (k + 1 <= q) ? v.y * inv : 0.f;
        v.z = (k + 2 <= q) ? v.z * inv : 0.f;
        v.w = (k + 3 <= q) ? v.w * inv : 0.f;
        *(float4*)(p + k) = v;
    }
}

// =====================================================================
extern "C" void kernel_launch(void* const* d_in, const int* in_sizes, int n_in,
                              void* d_out, int out_size)
{
    (void)in_sizes; (void)n_in; (void)out_size;
    const float* x  = (const float*)d_in[0];
    const float* Wq = (const float*)d_in[1];
    const float* bq = (const float*)d_in[2];
    const float* Wk = (const float*)d_in[3];
    const float* bk = (const float*)d_in[4];
    const float* Wv = (const float*)d_in[5];
    const float* bv = (const float*)d_in[6];
    const float* Wo = (const float*)d_in[7];
    const float* bo = (const float*)d_in[8];

    float* out   = (float*)d_out;
    float* probs = out + (size_t)MROWS * DMODEL;   // (out, attn_probs) tuple order

    static float *pQ = nullptr, *pK = nullptr, *pV = nullptr, *pAO = nullptr, *pL = nullptr;
    static bool inited = false;
    if (!inited) {
        cudaGetSymbolAddress((void**)&pQ,  g_q);
        cudaGetSymbolAddress((void**)&pK,  g_k);
        cudaGetSymbolAddress((void**)&pV,  g_v);
        cudaGetSymbolAddress((void**)&pAO, g_ao);
        cudaGetSymbolAddress((void**)&pL,  g_linv);
        cudaFuncSetAttribute(attn_kernel, cudaFuncAttributeMaxDynamicSharedMemorySize,
                             ATTN_SMEM_BYTES);
        inited = true;
    }

    dim3 gg(DMODEL / 128, MROWS / 128);   // (16, 32)
    gemm_kernel<0><<<gg, 256>>>(x, Wq, bq, pQ);
    gemm_kernel<0><<<gg, 256>>>(x, Wk, bk, pK);
    gemm_kernel<0><<<gg, 256>>>(x, Wv, bv, pV);

    attn_kernel<<<dim3(SEQ / 64, BHN), 256, ATTN_SMEM_BYTES>>>(pQ, pK, pV, probs, pAO, pL);

    rescale_kernel<<<BHN * SEQ, 128>>>(probs, pL);

    gemm_kernel<1><<<gg, 256>>>(pAO, Wo, bo, out);
}

// round 2
// speedup vs baseline: 1.1379x; 1.1379x over previous
#include <cuda_runtime.h>
#include <cstdint>
#include <math.h>

// Problem constants
#define HEADS   8
#define SEQ     2048
#define DMODEL  2048
#define HDIM    256
#define BATCH   2
#define BHN     (BATCH*HEADS)      // 16
#define MROWS   (BATCH*SEQ)        // 4096
#define SCALING 0.0625f            // 256^-0.5

// ---------------- scratch (device globals; no allocation) ----------------
__device__ float g_q[BHN*SEQ*HDIM];    // [bh][s][hd]
__device__ float g_k[BHN*SEQ*HDIM];
__device__ float g_v[BHN*SEQ*HDIM];
__device__ float g_ao[MROWS*DMODEL];   // attention output in [b,s,D] layout
__device__ float g_linv[BHN*SEQ];      // 1/rowsum
__device__ float g_m[BHN*SEQ];         // row max

// ---------------- helpers ----------------
__device__ __forceinline__ uint32_t f2tf32(float x) {
    uint32_t r;
    asm("cvt.rna.tf32.f32 %0, %1;" : "=r"(r) : "f"(x));
    return r;
}

__device__ __forceinline__ void mma_tf32(float c[4],
                                         uint32_t a0, uint32_t a1, uint32_t a2, uint32_t a3,
                                         uint32_t b0, uint32_t b1) {
    asm volatile(
        "mma.sync.aligned.m16n8k8.row.col.f32.tf32.tf32.f32 "
        "{%0,%1,%2,%3},{%4,%5,%6,%7},{%8,%9},{%0,%1,%2,%3};"
        : "+f"(c[0]), "+f"(c[1]), "+f"(c[2]), "+f"(c[3])
        : "r"(a0), "r"(a1), "r"(a2), "r"(a3), "r"(b0), "r"(b1));
}

__device__ __forceinline__ void cp16(void* smem, const void* gmem) {
    uint32_t s = (uint32_t)__cvta_generic_to_shared(smem);
    asm volatile("cp.async.cg.shared.global [%0], [%1], 16;" :: "r"(s), "l"(gmem) : "memory");
}
__device__ __forceinline__ void cp_commit() { asm volatile("cp.async.commit_group;" ::: "memory"); }
template<int N> __device__ __forceinline__ void cp_wait() {
    asm volatile("cp.async.wait_group %0;" :: "n"(N) : "memory");
}

// =====================================================================
// GEMM: Y[m,n] = sum_k A[m,k] * W[n,k] + bias[n]
// 128x128x32 tiles, 3-stage cp.async pipeline, raw fp32 in smem,
// RNA tf32 cvt at fragment load. MODE 0 -> [bh][s][hd], MODE 1 -> [m][n].
// =====================================================================
#define GST 36                    // smem row stride (floats), 16B-aligned
#define GHALF (128*GST)           // 4608 floats (A or B part of a stage)
#define GSTAGE (2*GHALF)          // 9216 floats per stage
#define GEMM_SMEM (3*GSTAGE*4)    // 110592 bytes

__device__ __forceinline__ void gemm_load_stage(float* gsm, int s,
                                                const float* A, const float* W,
                                                int m0, int n0, int k0, int tid)
{
    float* sA = gsm + s * GSTAGE;
    float* sB = sA + GHALF;
    #pragma unroll
    for (int c = 0; c < 4; c++) {
        int id = tid + 256 * c;          // 0..1023
        int r = id >> 3, ch = (id & 7) << 2;
        cp16(sA + r * GST + ch, A + (size_t)(m0 + r) * DMODEL + k0 + ch);
        cp16(sB + r * GST + ch, W + (size_t)(n0 + r) * DMODEL + k0 + ch);
    }
}

template <int MODE>
__global__ __launch_bounds__(256, 2)
void gemm_kernel(const float* __restrict__ A, const float* __restrict__ W,
                 const float* __restrict__ bias, float* __restrict__ out)
{
    extern __shared__ float gsm[];

    const int tid  = threadIdx.x;
    const int lane = tid & 31;
    const int warp = tid >> 5;
    const int wm = warp & 3;          // 4 warps along M (32 rows each)
    const int wn = warp >> 2;         // 2 warps along N (64 cols each)
    const int g  = lane >> 2;
    const int t4 = lane & 3;

    const int m0 = blockIdx.y * 128;
    const int n0 = blockIdx.x * 128;

    float c[2][8][4];
    #pragma unroll
    for (int i = 0; i < 2; i++)
        #pragma unroll
        for (int j = 0; j < 8; j++)
            #pragma unroll
            for (int r = 0; r < 4; r++) c[i][j][r] = 0.f;

    gemm_load_stage(gsm, 0, A, W, m0, n0, 0, tid);  cp_commit();
    gemm_load_stage(gsm, 1, A, W, m0, n0, 32, tid); cp_commit();

    const int NIT = DMODEL / 32;      // 64
    for (int i = 0; i < NIT; i++) {
        cp_wait<1>();
        __syncthreads();
        if (i + 2 < NIT) gemm_load_stage(gsm, (i + 2) % 3, A, W, m0, n0, (i + 2) * 32, tid);
        cp_commit();

        const float* sA = gsm + (i % 3) * GSTAGE;
        const float* sB = sA + GHALF;

        #pragma unroll
        for (int kk = 0; kk < 32; kk += 8) {
            uint32_t a[2][4];
            #pragma unroll
            for (int ii = 0; ii < 2; ii++) {
                int row = wm * 32 + ii * 16 + g;
                a[ii][0] = f2tf32(sA[row * GST + kk + t4]);
                a[ii][1] = f2tf32(sA[(row + 8) * GST + kk + t4]);
                a[ii][2] = f2tf32(sA[row * GST + kk + t4 + 4]);
                a[ii][3] = f2tf32(sA[(row + 8) * GST + kk + t4 + 4]);
            }
            uint32_t b[8][2];
            #pragma unroll
            for (int j = 0; j < 8; j++) {
                int col = wn * 64 + j * 8 + g;
                b[j][0] = f2tf32(sB[col * GST + kk + t4]);
                b[j][1] = f2tf32(sB[col * GST + kk + t4 + 4]);
            }
            #pragma unroll
            for (int ii = 0; ii < 2; ii++)
                #pragma unroll
                for (int j = 0; j < 8; j++)
                    mma_tf32(c[ii][j], a[ii][0], a[ii][1], a[ii][2], a[ii][3], b[j][0], b[j][1]);
        }
    }

    // epilogue
    #pragma unroll
    for (int i = 0; i < 2; i++) {
        #pragma unroll
        for (int j = 0; j < 8; j++) {
            int row0 = m0 + wm * 32 + i * 16 + g;
            int col  = n0 + wn * 64 + j * 8 + 2 * t4;
            float b0 = bias[col], b1 = bias[col + 1];
            float2 v0 = make_float2(c[i][j][0] + b0, c[i][j][1] + b1);
            float2 v1 = make_float2(c[i][j][2] + b0, c[i][j][3] + b1);
            if (MODE == 0) {
                int bb = row0 >> 11, s = row0 & 2047, h = col >> 8, dd = col & 255;
                size_t base = (((size_t)bb * HEADS + h) * SEQ) * HDIM + dd;
                *(float2*)(out + base + (size_t)s * HDIM)       = v0;
                *(float2*)(out + base + (size_t)(s + 8) * HDIM) = v1;
            } else {
                *(float2*)(out + (size_t)row0 * DMODEL + col)       = v0;
                *(float2*)(out + (size_t)(row0 + 8) * DMODEL + col) = v1;
            }
        }
    }
}

// =====================================================================
// Attention: single-pass flash (online softmax). Per (bh, 64-row q tile).
// K/V in 32-row tiles, cp.async double-buffered, raw fp32 in smem.
// Raw scaled scores s written to probs gmem; exp+normalize deferred to
// rescale kernel using per-row final max m and 1/l.
// =====================================================================
#define QW   260                       // sQ row stride (uint32 words)
#define KW   260                       // sK row stride
#define VW   264                       // sV row stride (conflict-free for row-varied frag loads)
#define PW   36                        // sP row stride
#define KSTG (32*KW)                   // 8320
#define VSTG (32*VW)                   // 8448
#define ATTN_SMEM_WORDS (64*QW + 2*KSTG + 2*VSTG + 64*PW)
#define ATTN_SMEM_BYTES (ATTN_SMEM_WORDS*4)

__device__ __forceinline__ void attn_prefetch(float* dK, float* dV,
                                              const float* Kg, const float* Vg, int tid)
{
    #pragma unroll
    for (int c = 0; c < 8; c++) {
        int id = tid + 256 * c;        // 0..2047
        int r = id >> 6, ch = (id & 63) << 2;
        cp16(dK + r * KW + ch, Kg + (size_t)r * HDIM + ch);
        cp16(dV + r * VW + ch, Vg + (size_t)r * HDIM + ch);
    }
}

__global__ __launch_bounds__(256, 1)
void attn_kernel(const float* __restrict__ Q, const float* __restrict__ Kp,
                 const float* __restrict__ Vp, float* __restrict__ probs,
                 float* __restrict__ ao, float* __restrict__ linv,
                 float* __restrict__ gmax)
{
    extern __shared__ uint32_t dyn[];
    uint32_t* sQ   = dyn;                                  // [64][QW] tf32
    float* sKbase  = (float*)(dyn + 64 * QW);              // 2 x [32][KW]
    float* sVbase  = (float*)(dyn + 64 * QW + 2 * KSTG);   // 2 x [32][VW]
    float* sP      = (float*)(dyn + 64 * QW + 2 * KSTG + 2 * VSTG);  // [64][PW]
    __shared__ float sRed[2][64];
    __shared__ float sSum[2][64];
    __shared__ float sMrun[64];
    __shared__ float sC[64];
    __shared__ float sL[64];
    __shared__ float sInv[64];

    const int tid = threadIdx.x, lane = tid & 31, warp = tid >> 5;
    const int wq = warp & 3;     // 4 warps along q (16 rows each)
    const int wk = warp >> 2;    // 2 warps along k-cols / hd halves
    const int g = lane >> 2, t4 = lane & 3;
    const int qt = gridDim.x - 1 - blockIdx.x;   // descending work order
    const int bh = blockIdx.y;
    const int q0 = qt * 64;
    const int nT = 2 * (qt + 1);

    // load Q tile (64 x 256), tf32 RNA
    const float* Qg = Q + ((size_t)bh * SEQ + q0) * HDIM;
    for (int i = tid; i < 64 * 64; i += 256) {
        int r = i >> 6, cc = (i & 63) << 2;
        float4 v = *(const float4*)(Qg + (size_t)r * HDIM + cc);
        sQ[r * QW + cc]     = f2tf32(v.x);
        sQ[r * QW + cc + 1] = f2tf32(v.y);
        sQ[r * QW + cc + 2] = f2tf32(v.z);
        sQ[r * QW + cc + 3] = f2tf32(v.w);
    }
    if (tid < 64) { sMrun[tid] = -INFINITY; sL[tid] = 0.f; }

    const float* Kh = Kp + (size_t)bh * SEQ * HDIM;
    const float* Vh = Vp + (size_t)bh * SEQ * HDIM;
    attn_prefetch(sKbase,        sVbase,        Kh,               Vh,               tid); cp_commit();
    attn_prefetch(sKbase + KSTG, sVbase + VSTG, Kh + 32 * HDIM,   Vh + 32 * HDIM,   tid); cp_commit();

    const int lr0 = wq * 16 + g, lr1 = lr0 + 8;
    const int r0g = q0 + lr0,    r1g = r0g + 8;
    float* pr0 = probs + ((size_t)bh * SEQ + r0g) * SEQ;
    float* pr1 = pr0 + 8 * SEQ;

    float o[16][4];
    #pragma unroll
    for (int nt = 0; nt < 16; nt++)
        #pragma unroll
        for (int r = 0; r < 4; r++) o[nt][r] = 0.f;

    for (int jj = 0; jj < nT; jj++) {
        const int st = jj & 1;
        const float* sK = sKbase + st * KSTG;
        const float* sV = sVbase + st * VSTG;

        cp_wait<1>();
        __syncthreads();                              // (1) stage ready

        // ---- S = Q K^T (64x32 tile; warp: 16 rows x 16 cols) ----
        float c4[2][4];
        #pragma unroll
        for (int nt = 0; nt < 2; nt++)
            #pragma unroll
            for (int r = 0; r < 4; r++) c4[nt][r] = 0.f;
        {
            const uint32_t* qa = sQ + lr0 * QW;
            const uint32_t* qb = sQ + lr1 * QW;
            const float* k0p = sK + (wk * 16 + g) * KW;
            const float* k1p = k0p + 8 * KW;
            #pragma unroll
            for (int kk = 0; kk < HDIM; kk += 8) {
                uint32_t a0 = qa[kk + t4], a1 = qb[kk + t4];
                uint32_t a2 = qa[kk + t4 + 4], a3 = qb[kk + t4 + 4];
                uint32_t b00 = f2tf32(k0p[kk + t4]), b01 = f2tf32(k0p[kk + t4 + 4]);
                uint32_t b10 = f2tf32(k1p[kk + t4]), b11 = f2tf32(k1p[kk + t4 + 4]);
                mma_tf32(c4[0], a0, a1, a2, a3, b00, b01);
                mma_tf32(c4[1], a0, a1, a2, a3, b10, b11);
            }
        }

        // ---- scale, write raw s to gmem, tile row max ----
        const int colbase = jj * 32 + wk * 16 + 2 * t4;    // global k col
        float s[2][4];
        float m0 = -INFINITY, m1 = -INFINITY;
        #pragma unroll
        for (int nt = 0; nt < 2; nt++) {
            s[nt][0] = c4[nt][0] * SCALING;
            s[nt][1] = c4[nt][1] * SCALING;
            s[nt][2] = c4[nt][2] * SCALING;
            s[nt][3] = c4[nt][3] * SCALING;
            int cg = colbase + nt * 8;
            if (cg     <= r0g && s[nt][0] > m0) m0 = s[nt][0];
            if (cg + 1 <= r0g && s[nt][1] > m0) m0 = s[nt][1];
            if (cg     <= r1g && s[nt][2] > m1) m1 = s[nt][2];
            if (cg + 1 <= r1g && s[nt][3] > m1) m1 = s[nt][3];
            *(float2*)(pr0 + cg) = make_float2(s[nt][0], s[nt][1]);
            *(float2*)(pr1 + cg) = make_float2(s[nt][2], s[nt][3]);
        }
        m0 = fmaxf(m0, __shfl_xor_sync(0xFFFFFFFFu, m0, 1));
        m0 = fmaxf(m0, __shfl_xor_sync(0xFFFFFFFFu, m0, 2));
        m1 = fmaxf(m1, __shfl_xor_sync(0xFFFFFFFFu, m1, 1));
        m1 = fmaxf(m1, __shfl_xor_sync(0xFFFFFFFFu, m1, 2));
        if (t4 == 0) { sRed[wk][lr0] = m0; sRed[wk][lr1] = m1; }
        __syncthreads();                              // (2)

        if (tid < 64) {
            float mt = fmaxf(sRed[0][tid], sRed[1][tid]);
            float mo = sMrun[tid];
            float mn = fmaxf(mo, mt);
            sMrun[tid] = mn;
            sC[tid] = __expf(mo - mn);
        }
        __syncthreads();                              // (3)

        // ---- e = exp(s - m_new), write to sP, partial sums, rescale o ----
        const float mr0 = sMrun[lr0], mr1 = sMrun[lr1];
        const float cc0 = sC[lr0],    cc1 = sC[lr1];
        float l0p = 0.f, l1p = 0.f;
        #pragma unroll
        for (int nt = 0; nt < 2; nt++) {
            int cg = colbase + nt * 8;
            int cl = wk * 16 + 2 * t4 + nt * 8;       // col within tile
            float e00 = (cg     <= r0g) ? __expf(s[nt][0] - mr0) : 0.f;
            float e01 = (cg + 1 <= r0g) ? __expf(s[nt][1] - mr0) : 0.f;
            float e10 = (cg     <= r1g) ? __expf(s[nt][2] - mr1) : 0.f;
            float e11 = (cg + 1 <= r1g) ? __expf(s[nt][3] - mr1) : 0.f;
            l0p += e00 + e01;  l1p += e10 + e11;
            *(float2*)(sP + lr0 * PW + cl) = make_float2(e00, e01);
            *(float2*)(sP + lr1 * PW + cl) = make_float2(e10, e11);
        }
        #pragma unroll
        for (int nt = 0; nt < 16; nt++) {
            o[nt][0] *= cc0; o[nt][1] *= cc0;
            o[nt][2] *= cc1; o[nt][3] *= cc1;
        }
        l0p += __shfl_xor_sync(0xFFFFFFFFu, l0p, 1);
        l0p += __shfl_xor_sync(0xFFFFFFFFu, l0p, 2);
        l1p += __shfl_xor_sync(0xFFFFFFFFu, l1p, 1);
        l1p += __shfl_xor_sync(0xFFFFFFFFu, l1p, 2);
        if (t4 == 0) { sSum[wk][lr0] = l0p; sSum[wk][lr1] = l1p; }
        __syncthreads();                              // (4)

        if (tid < 64) sL[tid] = sL[tid] * sC[tid] + sSum[0][tid] + sSum[1][tid];

        // ---- O += P @ V (warp: 16 rows x 128 hd cols) ----
        #pragma unroll
        for (int kk = 0; kk < 32; kk += 8) {
            uint32_t a0 = f2tf32(sP[lr0 * PW + kk + t4]);
            uint32_t a1 = f2tf32(sP[lr1 * PW + kk + t4]);
            uint32_t a2 = f2tf32(sP[lr0 * PW + kk + t4 + 4]);
            uint32_t a3 = f2tf32(sP[lr1 * PW + kk + t4 + 4]);
            #pragma unroll
            for (int nt = 0; nt < 16; nt++) {
                int vcol = wk * 128 + nt * 8 + g;
                uint32_t b0 = f2tf32(sV[(kk + t4) * VW + vcol]);
                uint32_t b1 = f2tf32(sV[(kk + t4 + 4) * VW + vcol]);
                mma_tf32(o[nt], a0, a1, a2, a3, b0, b1);
            }
        }
        __syncthreads();                              // (5) stage fully consumed

        if (jj + 2 < nT)
            attn_prefetch(sKbase + st * KSTG, sVbase + st * VSTG,
                          Kh + (size_t)(jj + 2) * 32 * HDIM,
                          Vh + (size_t)(jj + 2) * 32 * HDIM, tid);
        cp_commit();
    }

    if (tid < 64) {
        float inv = 1.0f / sL[tid];
        sInv[tid] = inv;
        linv[(size_t)bh * SEQ + q0 + tid] = inv;
        gmax[(size_t)bh * SEQ + q0 + tid] = sMrun[tid];
    }
    __syncthreads();

    // write O (scaled) to attn_out in [b, s, D] layout
    const float i0 = sInv[lr0];
    const float i1 = sInv[lr1];
    const int bb = bh >> 3, hh = bh & 7;
    float* og = ao + ((size_t)bb * SEQ + q0) * DMODEL + hh * HDIM;
    #pragma unroll
    for (int nt = 0; nt < 16; nt++) {
        int col = wk * 128 + nt * 8 + 2 * t4;
        *(float2*)(og + (size_t)lr0 * DMODEL + col) = make_float2(o[nt][0] * i0, o[nt][1] * i0);
        *(float2*)(og + (size_t)lr1 * DMODEL + col) = make_float2(o[nt][2] * i1, o[nt][3] * i1);
    }
}

// =====================================================================
// Rescale: probs[row][k] = exp(s - m) * inv for k <= q, else 0 (no read
// of the upper triangle). One block (256 thr) per row.
// =====================================================================
__global__ void rescale_kernel(float* __restrict__ probs,
                               const float* __restrict__ gmax,
                               const float* __restrict__ linv)
{
    int row = blockIdx.x;                 // bh*SEQ + q
    int q = row & (SEQ - 1);
    float m = gmax[row];
    float inv = linv[row];
    float* p = probs + (size_t)row * SEQ;
    for (int k = threadIdx.x * 4; k < SEQ; k += 1024) {
        float4 v;
        if (k + 3 <= q) {
            v = *(float4*)(p + k);
            v.x = __expf(v.x - m) * inv;
            v.y = __expf(v.y - m) * inv;
            v.z = __expf(v.z - m) * inv;
            v.w = __expf(v.w - m) * inv;
        } else if (k > q) {
            v = make_float4(0.f, 0.f, 0.f, 0.f);
        } else {
            v = *(float4*)(p + k);
            v.x = (k     <= q) ? __expf(v.x - m) * inv : 0.f;
            v.y = (k + 1 <= q) ? __expf(v.y - m) * inv : 0.f;
            v.z = (k + 2 <= q) ? __expf(v.z - m) * inv : 0.f;
            v.w = (k + 3 <= q) ? __expf(v.w - m) * inv : 0.f;
        }
        *(float4*)(p + k) = v;
    }
}

// =====================================================================
extern "C" void kernel_launch(void* const* d_in, const int* in_sizes, int n_in,
                              void* d_out, int out_size)
{
    (void)in_sizes; (void)n_in; (void)out_size;
    const float* x  = (const float*)d_in[0];
    const float* Wq = (const float*)d_in[1];
    const float* bq = (const float*)d_in[2];
    const float* Wk = (const float*)d_in[3];
    const float* bk = (const float*)d_in[4];
    const float* Wv = (const float*)d_in[5];
    const float* bv = (const float*)d_in[6];
    const float* Wo = (const float*)d_in[7];
    const float* bo = (const float*)d_in[8];

    float* out   = (float*)d_out;
    float* probs = out + (size_t)MROWS * DMODEL;   // (out, attn_probs) tuple order

    static float *pQ = nullptr, *pK = nullptr, *pV = nullptr, *pAO = nullptr,
                 *pL = nullptr, *pM = nullptr;
    static bool inited = false;
    if (!inited) {
        cudaGetSymbolAddress((void**)&pQ,  g_q);
        cudaGetSymbolAddress((void**)&pK,  g_k);
        cudaGetSymbolAddress((void**)&pV,  g_v);
        cudaGetSymbolAddress((void**)&pAO, g_ao);
        cudaGetSymbolAddress((void**)&pL,  g_linv);
        cudaGetSymbolAddress((void**)&pM,  g_m);
        cudaFuncSetAttribute(attn_kernel, cudaFuncAttributeMaxDynamicSharedMemorySize,
                             ATTN_SMEM_BYTES);
        cudaFuncSetAttribute(gemm_kernel<0>, cudaFuncAttributeMaxDynamicSharedMemorySize,
                             GEMM_SMEM);
        cudaFuncSetAttribute(gemm_kernel<1>, cudaFuncAttributeMaxDynamicSharedMemorySize,
                             GEMM_SMEM);
        inited = true;
    }

    dim3 gg(DMODEL / 128, MROWS / 128);   // (16, 32)
    gemm_kernel<0><<<gg, 256, GEMM_SMEM>>>(x, Wq, bq, pQ);
    gemm_kernel<0><<<gg, 256, GEMM_SMEM>>>(x, Wk, bk, pK);
    gemm_kernel<0><<<gg, 256, GEMM_SMEM>>>(x, Wv, bv, pV);

    attn_kernel<<<dim3(SEQ / 64, BHN), 256, ATTN_SMEM_BYTES>>>(pQ, pK, pV, probs, pAO, pL, pM);

    rescale_kernel<<<BHN * SEQ, 256>>>(probs, pM, pL);

    gemm_kernel<1><<<gg, 256, GEMM_SMEM>>>(pAO, Wo, bo, out);
}